// round 10
// baseline (speedup 1.0000x reference)
#include <cuda_runtime.h>
#include <cuda_fp16.h>
#include <cuda_bf16.h>

// Pairwise max-margin hinge loss, fp16x2 with fused HFMA2.RELU.
// Grid: 1056 blocks = 528 unordered 32x32 tile-pairs x 2 batch-halves.
// Each block: one tile-pair, 16 batches, 256 threads (8 warps x 2 batches).
// Native [N,B] layout is contiguous per tile row -> coalesced staging.
// loss = [2*offdiag + diag] / (N*2).
// Inputs: out [N,B] f32, label [N,B] f32, margin [1] f32.  N=1024, B=32.

#define PN 1024
#define PB 32
#define NBLK (528 * 2)
#define THREADS 256
#define BH 16              // batches per block
#define JSTRIDE 33         // half J arrays, [b][j]
#define KSTRIDE 40         // half K arrays, [b][k]: 80B row, 16B-aligned

__global__ __launch_bounds__(THREADS)
void hinge_tile_kernel(const float* __restrict__ g_out,
                       const float* __restrict__ g_label,
                       const float* __restrict__ g_margin,
                       float* __restrict__ result)
{
    __shared__ __half s_oJ[BH * JSTRIDE];               // +o, [b][j]
    __shared__ __half s_lJ[BH * JSTRIDE];               // +l, [b][j]
    __shared__ alignas(16) __half s_oK[BH * KSTRIDE];   // +o, [b][k]
    __shared__ alignas(16) __half s_lK[BH * KSTRIDE];   // +l, [b][k]
    __shared__ float warp_sums[THREADS / 32];

    const int p = blockIdx.x >> 1;      // 0..527: unordered tile pair
    const int h = blockIdx.x & 1;       // batch half: 0 -> b 0..15, 1 -> b 16..31

    int jt, kt;
    float w;
    if (p < 480)      { int dt = (p >> 5) + 1; jt = p & 31; kt = (jt + dt) & 31; w = 2.0f; }
    else if (p < 496) { jt = p - 480; kt = jt + 16; w = 2.0f; }
    else              { jt = p - 496; kt = jt;      w = 1.0f; }

    const int t    = threadIdx.x;
    const int wid  = t >> 5;
    const int lane = t & 31;

    // Stage: tile r, batches [h*16, h*16+16). Row n of tile r lives at
    // gmem offset (r*32+n)*32 + b. 64B contiguous per (n, batch-half).
    {
        const float* Jo = g_out   + jt * 1024 + h * BH;
        const float* Jl = g_label + jt * 1024 + h * BH;
        const float* Ko = g_out   + kt * 1024 + h * BH;
        const float* Kl = g_label + kt * 1024 + h * BH;
        #pragma unroll
        for (int q = 0; q < 2; q++) {
            int e = t + q * THREADS;    // 0..511 = n*16 + b_local
            int n = e >> 4;
            int b = e & 15;
            int g = n * PB + b;
            s_oJ[b * JSTRIDE + n] = __float2half(Jo[g]);
            s_lJ[b * JSTRIDE + n] = __float2half(Jl[g]);
            s_oK[b * KSTRIDE + n] = __float2half(Ko[g]);
            s_lK[b * KSTRIDE + n] = __float2half(Kl[g]);
        }
    }
    __syncthreads();

    const __half2 m2 = __float2half2_rn(g_margin[0]);

    float acc = 0.0f;

    // Warp wid handles batches {2*wid, 2*wid+1}; lane = j row in the J tile.
    #pragma unroll
    for (int i = 0; i < 2; i++) {
        const int bb = wid * 2 + i;
        const __half2 oj2 = __half2half2(s_oJ[bb * JSTRIDE + lane]);
        const __half2 lj2 = __half2half2(s_lJ[bb * JSTRIDE + lane]);
        const uint4* ko = (const uint4*)(s_oK + bb * KSTRIDE);
        const uint4* kl = (const uint4*)(s_lK + bb * KSTRIDE);

        __half2 a0 = __float2half2_rn(0.f), a1 = a0, a2 = a0, a3 = a0;

        #pragma unroll
        for (int g = 0; g < 4; g++) {   // 8 k per group
            uint4 o4 = ko[g];           // LDS.128 broadcast (uniform address)
            uint4 l4 = kl[g];
            const __half2 ox = *(const __half2*)&o4.x, oy = *(const __half2*)&o4.y;
            const __half2 oz = *(const __half2*)&o4.z, ow = *(const __half2*)&o4.w;
            const __half2 lx = *(const __half2*)&l4.x, ly = *(const __half2*)&l4.y;
            const __half2 lz = *(const __half2*)&l4.z, lw = *(const __half2*)&l4.w;

            // relu(m + (ok-oj)*(lj-lk)) fused into HFMA2.RELU
            a0 = __hadd2(a0, __hfma2_relu(__hsub2(ox, oj2), __hsub2(lj2, lx), m2));
            a1 = __hadd2(a1, __hfma2_relu(__hsub2(oy, oj2), __hsub2(lj2, ly), m2));
            a2 = __hadd2(a2, __hfma2_relu(__hsub2(oz, oj2), __hsub2(lj2, lz), m2));
            a3 = __hadd2(a3, __hfma2_relu(__hsub2(ow, oj2), __hsub2(lj2, lw), m2));
        }

        float2 f0 = __half22float2(a0);
        float2 f1 = __half22float2(a1);
        float2 f2 = __half22float2(a2);
        float2 f3 = __half22float2(a3);
        acc += ((f0.x + f0.y) + (f1.x + f1.y)) + ((f2.x + f2.y) + (f3.x + f3.y));
    }
    acc *= w;

    // Warp reduce.
    #pragma unroll
    for (int off = 16; off > 0; off >>= 1)
        acc += __shfl_xor_sync(0xFFFFFFFFu, acc, off);
    if (lane == 0) warp_sums[wid] = acc;
    __syncthreads();

    if (t == 0) {
        float s = 0.f;
        #pragma unroll
        for (int wdx = 0; wdx < THREADS / 32; wdx++) s += warp_sums[wdx];
        atomicAdd(result, s * (1.0f / (2.0f * PN)));
    }
}

extern "C" void kernel_launch(void* const* d_in, const int* in_sizes, int n_in,
                              void* d_out, int out_size)
{
    const float* g_out    = (const float*)d_in[0];
    const float* g_label  = (const float*)d_in[1];
    const float* g_margin = (const float*)d_in[2];
    float*       result   = (float*)d_out;

    cudaMemsetAsync(result, 0, sizeof(float));
    hinge_tile_kernel<<<NBLK, THREADS>>>(g_out, g_label, g_margin, result);
}

// round 11
// speedup vs baseline: 1.0088x; 1.0088x over previous
#include <cuda_runtime.h>
#include <cuda_fp16.h>
#include <cuda_bf16.h>

// Pairwise max-margin hinge loss, fp16 HFMA2.RELU, no-smem mainloop.
// prep: transpose+convert to half [B][N] (device scratch) and zero d_out.
// main: 1056 blocks = 528 unordered 32x32 tile-pairs x 2 batch-halves;
//       8 warps/block, warp handles 2 batches; J values via coalesced LDG,
//       K rows via warp-uniform LDG.128 (L2-hot).
// loss = [2*offdiag + diag] / (N*2).
// Inputs: out [N,B] f32, label [N,B] f32, margin [1] f32.  N=1024, B=32.

#define PN 1024
#define PB 32
#define NBLK (528 * 2)
#define THREADS 256

__device__ __align__(16) __half g_oh[PB][PN];   // +o, [b][n]
__device__ __align__(16) __half g_lh[PB][PN];   // +l, [b][n]

__global__ __launch_bounds__(256)
void prep_kernel(const float* __restrict__ g_out,
                 const float* __restrict__ g_label,
                 float* __restrict__ result)
{
    int idx = blockIdx.x * blockDim.x + threadIdx.x;   // 0 .. PN*PB-1
    if (idx < PN * PB) {
        int n = idx >> 5;       // coalesced read of [N,B] rows
        int b = idx & 31;
        g_oh[b][n] = __float2half(g_out[idx]);
        g_lh[b][n] = __float2half(g_label[idx]);
    }
    if (idx == 0) *result = 0.0f;
}

__global__ __launch_bounds__(THREADS)
void hinge_tile_kernel(const float* __restrict__ g_margin,
                       float* __restrict__ result)
{
    __shared__ float warp_sums[THREADS / 32];

    const int p = blockIdx.x >> 1;      // 0..527: unordered tile pair
    const int h = blockIdx.x & 1;       // batch half

    int jt, kt;
    float w;
    if (p < 480)      { int dt = (p >> 5) + 1; jt = p & 31; kt = (jt + dt) & 31; w = 2.0f; }
    else if (p < 496) { jt = p - 480; kt = jt + 16; w = 2.0f; }
    else              { jt = p - 496; kt = jt;      w = 1.0f; }

    const int t    = threadIdx.x;
    const int wid  = t >> 5;
    const int lane = t & 31;

    const __half2 m2 = __float2half2_rn(g_margin[0]);

    float acc = 0.0f;

    // Warp handles batches h*16 + 2*wid + {0,1}; lane = j row in the J tile.
    #pragma unroll
    for (int i = 0; i < 2; i++) {
        const int bb = h * 16 + wid * 2 + i;

        // J: coalesced 64B loads (lane -> consecutive half).
        const __half2 oj2 = __half2half2(g_oh[bb][jt * 32 + lane]);
        const __half2 lj2 = __half2half2(g_lh[bb][jt * 32 + lane]);

        // K row: 64B = 4 x uint4, warp-uniform addresses (1 sector each).
        const uint4* ko = (const uint4*)(&g_oh[bb][kt * 32]);
        const uint4* kl = (const uint4*)(&g_lh[bb][kt * 32]);

        __half2 a0 = __float2half2_rn(0.f), a1 = a0, a2 = a0, a3 = a0;

        #pragma unroll
        for (int g = 0; g < 4; g++) {   // 8 k per group
            uint4 o4 = __ldg(&ko[g]);
            uint4 l4 = __ldg(&kl[g]);
            const __half2 ox = *(const __half2*)&o4.x, oy = *(const __half2*)&o4.y;
            const __half2 oz = *(const __half2*)&o4.z, ow = *(const __half2*)&o4.w;
            const __half2 lx = *(const __half2*)&l4.x, ly = *(const __half2*)&l4.y;
            const __half2 lz = *(const __half2*)&l4.z, lw = *(const __half2*)&l4.w;

            // relu(m + (ok-oj)*(lj-lk)) fused into HFMA2.RELU
            a0 = __hadd2(a0, __hfma2_relu(__hsub2(ox, oj2), __hsub2(lj2, lx), m2));
            a1 = __hadd2(a1, __hfma2_relu(__hsub2(oy, oj2), __hsub2(lj2, ly), m2));
            a2 = __hadd2(a2, __hfma2_relu(__hsub2(oz, oj2), __hsub2(lj2, lz), m2));
            a3 = __hadd2(a3, __hfma2_relu(__hsub2(ow, oj2), __hsub2(lj2, lw), m2));
        }

        float2 f0 = __half22float2(a0);
        float2 f1 = __half22float2(a1);
        float2 f2 = __half22float2(a2);
        float2 f3 = __half22float2(a3);
        acc += ((f0.x + f0.y) + (f1.x + f1.y)) + ((f2.x + f2.y) + (f3.x + f3.y));
    }
    acc *= w;

    // Warp reduce.
    #pragma unroll
    for (int off = 16; off > 0; off >>= 1)
        acc += __shfl_xor_sync(0xFFFFFFFFu, acc, off);
    if (lane == 0) warp_sums[wid] = acc;
    __syncthreads();

    if (t == 0) {
        float s = 0.f;
        #pragma unroll
        for (int wdx = 0; wdx < THREADS / 32; wdx++) s += warp_sums[wdx];
        atomicAdd(result, s * (1.0f / (2.0f * PN)));
    }
}

extern "C" void kernel_launch(void* const* d_in, const int* in_sizes, int n_in,
                              void* d_out, int out_size)
{
    const float* g_out    = (const float*)d_in[0];
    const float* g_label  = (const float*)d_in[1];
    const float* g_margin = (const float*)d_in[2];
    float*       result   = (float*)d_out;

    prep_kernel<<<(PN * PB + 255) / 256, 256>>>(g_out, g_label, result);
    hinge_tile_kernel<<<NBLK, THREADS>>>(g_margin, result);
}

// round 12
// speedup vs baseline: 1.0363x; 1.0272x over previous
#include <cuda_runtime.h>
#include <cuda_fp16.h>
#include <cuda_bf16.h>

// Pairwise max-margin hinge loss. SINGLE kernel:
// - 528 blocks = unordered 32x32 tile-pairs, each covering all 32 batches.
// - fp16 smem tiles, HFMA2.RELU fused hinge, LDS.128 broadcast inner loop.
// - last-block finalize: no memset, no prep kernel, 1 graph node.
// loss = [2*offdiag + diag] / (N*2).
// Inputs: out [N,B] f32, label [N,B] f32, margin [1] f32.  N=1024, B=32.

#define PN 1024
#define PB 32
#define NBLK 528
#define THREADS 512        // 16 warps; warp w -> batches 2w, 2w+1
#define JSTRIDE 33         // half J arrays, [b][j]
#define KSTRIDE 40         // half K arrays, [b][k]: 80B rows, 16B-aligned

__device__ float    g_acc = 0.0f;   // cross-block accumulator
__device__ unsigned g_cnt = 0u;     // blocks-done counter

__global__ __launch_bounds__(THREADS)
void hinge_tile_kernel(const float* __restrict__ g_out,
                       const float* __restrict__ g_label,
                       const float* __restrict__ g_margin,
                       float* __restrict__ result)
{
    __shared__ __half s_oJ[PB * JSTRIDE];               // +o, [b][j]
    __shared__ __half s_lJ[PB * JSTRIDE];               // +l, [b][j]
    __shared__ alignas(16) __half s_oK[PB * KSTRIDE];   // +o, [b][k]
    __shared__ alignas(16) __half s_lK[PB * KSTRIDE];   // +l, [b][k]
    __shared__ float warp_sums[THREADS / 32];

    const int p = blockIdx.x;           // 0..527: unordered tile pair
    int jt, kt;
    float w;
    if (p < 480)      { int dt = (p >> 5) + 1; jt = p & 31; kt = (jt + dt) & 31; w = 2.0f; }
    else if (p < 496) { jt = p - 480; kt = jt + 16; w = 2.0f; }
    else              { jt = p - 496; kt = jt;      w = 1.0f; }

    const int t    = threadIdx.x;
    const int wid  = t >> 5;
    const int lane = t & 31;

    // Stage: tile r covers gmem [r*1024, r*1024+1024): contiguous, coalesced.
    {
        const float* Jo = g_out   + jt * 1024;
        const float* Jl = g_label + jt * 1024;
        const float* Ko = g_out   + kt * 1024;
        const float* Kl = g_label + kt * 1024;
        #pragma unroll
        for (int q = 0; q < 2; q++) {
            int g = t + q * THREADS;    // 0..1023 = n_local*32 + b
            int n = g >> 5;
            int b = g & 31;
            s_oJ[b * JSTRIDE + n] = __float2half(Jo[g]);
            s_lJ[b * JSTRIDE + n] = __float2half(Jl[g]);
            s_oK[b * KSTRIDE + n] = __float2half(Ko[g]);
            s_lK[b * KSTRIDE + n] = __float2half(Kl[g]);
        }
    }
    __syncthreads();

    const __half2 m2 = __float2half2_rn(g_margin[0]);

    float acc = 0.0f;

    // Warp wid handles batches {2*wid, 2*wid+1}; lane = j row in the J tile.
    #pragma unroll
    for (int i = 0; i < 2; i++) {
        const int bb = wid * 2 + i;
        const __half2 oj2 = __half2half2(s_oJ[bb * JSTRIDE + lane]);
        const __half2 lj2 = __half2half2(s_lJ[bb * JSTRIDE + lane]);
        const uint4* ko = (const uint4*)(s_oK + bb * KSTRIDE);
        const uint4* kl = (const uint4*)(s_lK + bb * KSTRIDE);

        __half2 a0 = __float2half2_rn(0.f), a1 = a0, a2 = a0, a3 = a0;

        #pragma unroll
        for (int g = 0; g < 4; g++) {   // 8 k per group
            uint4 o4 = ko[g];           // LDS.128, warp-uniform broadcast
            uint4 l4 = kl[g];
            const __half2 ox = *(const __half2*)&o4.x, oy = *(const __half2*)&o4.y;
            const __half2 oz = *(const __half2*)&o4.z, ow = *(const __half2*)&o4.w;
            const __half2 lx = *(const __half2*)&l4.x, ly = *(const __half2*)&l4.y;
            const __half2 lz = *(const __half2*)&l4.z, lw = *(const __half2*)&l4.w;

            // relu(m + (ok-oj)*(lj-lk)) fused into HFMA2.RELU
            a0 = __hadd2(a0, __hfma2_relu(__hsub2(ox, oj2), __hsub2(lj2, lx), m2));
            a1 = __hadd2(a1, __hfma2_relu(__hsub2(oy, oj2), __hsub2(lj2, ly), m2));
            a2 = __hadd2(a2, __hfma2_relu(__hsub2(oz, oj2), __hsub2(lj2, lz), m2));
            a3 = __hadd2(a3, __hfma2_relu(__hsub2(ow, oj2), __hsub2(lj2, lw), m2));
        }

        float2 f0 = __half22float2(a0);
        float2 f1 = __half22float2(a1);
        float2 f2 = __half22float2(a2);
        float2 f3 = __half22float2(a3);
        acc += ((f0.x + f0.y) + (f1.x + f1.y)) + ((f2.x + f2.y) + (f3.x + f3.y));
    }
    acc *= w;

    // Warp reduce.
    #pragma unroll
    for (int off = 16; off > 0; off >>= 1)
        acc += __shfl_xor_sync(0xFFFFFFFFu, acc, off);
    if (lane == 0) warp_sums[wid] = acc;
    __syncthreads();

    // Block partial -> global accumulator; last block finalizes and resets
    // state so the kernel is replay-deterministic under graph capture.
    if (t == 0) {
        float s = 0.f;
        #pragma unroll
        for (int wdx = 0; wdx < THREADS / 32; wdx++) s += warp_sums[wdx];
        atomicAdd(&g_acc, s);
        __threadfence();
        unsigned done = atomicAdd(&g_cnt, 1u);
        if (done == NBLK - 1) {
            float total = atomicExch(&g_acc, 0.0f);   // read + reset
            *result = total * (1.0f / (2.0f * PN));
            g_cnt = 0u;                               // reset for next replay
            __threadfence();
        }
    }
}

extern "C" void kernel_launch(void* const* d_in, const int* in_sizes, int n_in,
                              void* d_out, int out_size)
{
    const float* g_out    = (const float*)d_in[0];
    const float* g_label  = (const float*)d_in[1];
    const float* g_margin = (const float*)d_in[2];
    float*       result   = (float*)d_out;

    hinge_tile_kernel<<<NBLK, THREADS>>>(g_out, g_label, g_margin, result);
}

// round 13
// speedup vs baseline: 1.0752x; 1.0376x over previous
#include <cuda_runtime.h>
#include <cuda_fp16.h>
#include <cuda_bf16.h>

// Pairwise max-margin hinge loss, fp16 batch-pair-packed HFMA2.RELU.
// Grid: 1056 blocks = 528 unordered 32x32 tile-pairs x 2 batch-halves.
// Block: 256 threads (8 warps), 16 batches = 8 batch-pairs; warp w -> pair w.
// half2 lanes hold (batch b0, batch b1); each HFMA2.RELU evaluates the hinge
// for 2 batches at one (j,k).  loss = [2*offdiag + diag] / (N*2).
// Inputs: out [N,B] f32, label [N,B] f32, margin [1] f32.  N=1024, B=32.

#define PN 1024
#define PB 32
#define NBLK (528 * 2)
#define THREADS 256
#define BH 16              // batches per block (8 pairs)
#define JS2 33             // J stride in half2 units (132B rows)
#define KS2 36             // K stride in half2 units (144B rows, 16B-aligned)

__global__ __launch_bounds__(THREADS)
void hinge_tile_kernel(const float* __restrict__ g_out,
                       const float* __restrict__ g_label,
                       const float* __restrict__ g_margin,
                       float* __restrict__ result)
{
    // Layout: [batch-pair][n] of half2 {b0, b1}.
    __shared__ __half s_oJ[(BH / 2) * JS2 * 2];
    __shared__ __half s_lJ[(BH / 2) * JS2 * 2];
    __shared__ alignas(16) __half s_oK[(BH / 2) * KS2 * 2];
    __shared__ alignas(16) __half s_lK[(BH / 2) * KS2 * 2];
    __shared__ float warp_sums[THREADS / 32];

    const int p = blockIdx.x >> 1;      // 0..527: unordered tile pair
    const int h = blockIdx.x & 1;       // batch half

    int jt, kt;
    float w;
    if (p < 480)      { int dt = (p >> 5) + 1; jt = p & 31; kt = (jt + dt) & 31; w = 2.0f; }
    else if (p < 496) { jt = p - 480; kt = jt + 16; w = 2.0f; }
    else              { jt = p - 496; kt = jt;      w = 1.0f; }

    const int t    = threadIdx.x;
    const int wid  = t >> 5;
    const int lane = t & 31;

    // Stage batches [h*16, h*16+16) of tiles jt (J) and kt (K).
    // Row n of tile r is at gmem (r*32+n)*32 + b : coalesced 64B segments.
    {
        const float* Jo = g_out   + jt * 1024 + h * BH;
        const float* Jl = g_label + jt * 1024 + h * BH;
        const float* Ko = g_out   + kt * 1024 + h * BH;
        const float* Kl = g_label + kt * 1024 + h * BH;
        #pragma unroll
        for (int q = 0; q < 2; q++) {
            int e  = t + q * THREADS;   // 0..511 = n*16 + bl
            int n  = e >> 4;
            int bl = e & 15;
            int bp = bl >> 1;
            int hi = bl & 1;
            int g  = n * PB + bl;
            s_oJ[(bp * JS2 + n) * 2 + hi] = __float2half(Jo[g]);
            s_lJ[(bp * JS2 + n) * 2 + hi] = __float2half(Jl[g]);
            s_oK[(bp * KS2 + n) * 2 + hi] = __float2half(Ko[g]);
            s_lK[(bp * KS2 + n) * 2 + hi] = __float2half(Kl[g]);
        }
    }
    __syncthreads();

    const __half2 m2 = __float2half2_rn(g_margin[0]);

    // Warp wid owns batch-pair wid; lane = j row in the J tile.
    const __half2 oj2 = ((const __half2*)s_oJ)[wid * JS2 + lane];  // {o[b0][j], o[b1][j]}
    const __half2 lj2 = ((const __half2*)s_lJ)[wid * JS2 + lane];
    const uint4* ko = (const uint4*)(s_oK + wid * KS2 * 2);        // 4 k per uint4
    const uint4* kl = (const uint4*)(s_lK + wid * KS2 * 2);

    __half2 a0 = __float2half2_rn(0.f), a1 = a0, a2 = a0, a3 = a0;

    #pragma unroll
    for (int g = 0; g < 8; g++) {       // 4 k per group, 32 k total
        uint4 o4 = ko[g];               // LDS.128, warp-uniform broadcast
        uint4 l4 = kl[g];
        const __half2 ox = *(const __half2*)&o4.x, oy = *(const __half2*)&o4.y;
        const __half2 oz = *(const __half2*)&o4.z, ow = *(const __half2*)&o4.w;
        const __half2 lx = *(const __half2*)&l4.x, ly = *(const __half2*)&l4.y;
        const __half2 lz = *(const __half2*)&l4.z, lw = *(const __half2*)&l4.w;

        // relu(m + (ok-oj)*(lj-lk)), both batches at once.
        a0 = __hadd2(a0, __hfma2_relu(__hsub2(ox, oj2), __hsub2(lj2, lx), m2));
        a1 = __hadd2(a1, __hfma2_relu(__hsub2(oy, oj2), __hsub2(lj2, ly), m2));
        a2 = __hadd2(a2, __hfma2_relu(__hsub2(oz, oj2), __hsub2(lj2, lz), m2));
        a3 = __hadd2(a3, __hfma2_relu(__hsub2(ow, oj2), __hsub2(lj2, lw), m2));
    }

    float2 f0 = __half22float2(a0);
    float2 f1 = __half22float2(a1);
    float2 f2 = __half22float2(a2);
    float2 f3 = __half22float2(a3);
    float acc = (((f0.x + f0.y) + (f1.x + f1.y))
               + ((f2.x + f2.y) + (f3.x + f3.y))) * w;

    // Warp reduce.
    #pragma unroll
    for (int off = 16; off > 0; off >>= 1)
        acc += __shfl_xor_sync(0xFFFFFFFFu, acc, off);
    if (lane == 0) warp_sums[wid] = acc;
    __syncthreads();

    if (t == 0) {
        float s = 0.f;
        #pragma unroll
        for (int wdx = 0; wdx < THREADS / 32; wdx++) s += warp_sums[wdx];
        atomicAdd(result, s * (1.0f / (2.0f * PN)));
    }
}

extern "C" void kernel_launch(void* const* d_in, const int* in_sizes, int n_in,
                              void* d_out, int out_size)
{
    const float* g_out    = (const float*)d_in[0];
    const float* g_label  = (const float*)d_in[1];
    const float* g_margin = (const float*)d_in[2];
    float*       result   = (float*)d_out;

    cudaMemsetAsync(result, 0, sizeof(float));
    hinge_tile_kernel<<<NBLK, THREADS>>>(g_out, g_label, g_margin, result);
}